// round 6
// baseline (speedup 1.0000x reference)
#include <cuda_runtime.h>
#include <math.h>

// Problem constants
static const int BB = 64, TT = 256, VV = 65, EE = 384, HH = 6, LLAY = 6, DD = 64, FF = 1536;
static const int NTOK = BB * TT; // 16384

// ---------------- scratch (no allocation allowed -> device globals) ----------
__device__ __align__(16) float g_x  [16384 * 384];
__device__ __align__(16) float g_h  [16384 * 384];
__device__ __align__(16) float g_q  [16384 * 384];
__device__ __align__(16) float g_k  [16384 * 384];
__device__ __align__(16) float g_v  [16384 * 384];
__device__ __align__(16) float g_att[16384 * 384];
__device__ __align__(16) float g_f  [16384 * 1536];
__device__ __align__(16) float g_logits[16384 * 65];
__device__ __align__(16) float g_loss[1];

// ---------------- embedding: x = tok_emb[idx] + pos_emb --------------------
__global__ void k_embed(const int* __restrict__ idx, const float* __restrict__ tok,
                        const float* __restrict__ pos, float* __restrict__ x) {
    int i = blockIdx.x * blockDim.x + threadIdx.x;
    if (i >= NTOK * EE) return;
    int n = i / EE, e = i - n * EE;
    int t = n % TT;
    x[i] = tok[idx[n] * EE + e] + pos[t * EE + e];
}

// ---------------- LayerNorm: warp per row (E=384 = 12 floats/lane) ----------
__global__ void k_ln(const float* __restrict__ x, const float* __restrict__ g,
                     const float* __restrict__ b, float* __restrict__ y) {
    int warp = threadIdx.x >> 5, lane = threadIdx.x & 31;
    int row = blockIdx.x * 8 + warp;
    if (row >= NTOK) return;
    const float4* xr = (const float4*)(x + row * EE);
    float4 v[3];
#pragma unroll
    for (int i = 0; i < 3; i++) v[i] = xr[lane + i * 32];
    float s = 0.f, s2 = 0.f;
#pragma unroll
    for (int i = 0; i < 3; i++) {
        s  += v[i].x + v[i].y + v[i].z + v[i].w;
        s2 += v[i].x * v[i].x + v[i].y * v[i].y + v[i].z * v[i].z + v[i].w * v[i].w;
    }
#pragma unroll
    for (int off = 16; off > 0; off >>= 1) {
        s  += __shfl_xor_sync(0xffffffffu, s,  off);
        s2 += __shfl_xor_sync(0xffffffffu, s2, off);
    }
    float mu = s * (1.f / EE);
    float var = s2 * (1.f / EE) - mu * mu;
    float rs = rsqrtf(var + 1e-5f);
    float4* yr = (float4*)(y + row * EE);
    const float4* gr = (const float4*)g;
    const float4* br = (const float4*)b;
#pragma unroll
    for (int i = 0; i < 3; i++) {
        float4 gg = gr[lane + i * 32], bb = br[lane + i * 32];
        float4 o;
        o.x = (v[i].x - mu) * rs * gg.x + bb.x;
        o.y = (v[i].y - mu) * rs * gg.y + bb.y;
        o.z = (v[i].z - mu) * rs * gg.z + bb.z;
        o.w = (v[i].w - mu) * rs * gg.w + bb.w;
        yr[lane + i * 32] = o;
    }
}

// ---------------- SGEMM: C[N,M] = A[N,K] @ W[K,M] (+bias)(+res)(relu) -------
// 128x128 tile, BK=16, 256 threads, 8x8 per thread.
template <bool GM>
__global__ void __launch_bounds__(256) k_gemm(
    const float* __restrict__ A, const float* __restrict__ W,
    const float* __restrict__ bias, const float* __restrict__ res,
    float* __restrict__ C, int K, int M, int relu)
{
    __shared__ float As[16][132];   // [k][n], padded
    __shared__ float Bs[16][128];   // [k][m]
    const int n0 = blockIdx.y * 128;
    const int m0 = blockIdx.x * 128;
    const int tid = threadIdx.x;
    const int tx = tid & 15, ty = tid >> 4;
    float acc[8][8];
#pragma unroll
    for (int i = 0; i < 8; i++)
#pragma unroll
        for (int j = 0; j < 8; j++) acc[i][j] = 0.f;

    for (int k0 = 0; k0 < K; k0 += 16) {
        // A tile: 128 rows x 16 k, via float4
#pragma unroll
        for (int i = 0; i < 2; i++) {
            int idx = tid + i * 256;
            int row = idx >> 2, c4 = idx & 3;
            float4 a = *(const float4*)(A + (size_t)(n0 + row) * K + k0 + c4 * 4);
            As[c4 * 4 + 0][row] = a.x;
            As[c4 * 4 + 1][row] = a.y;
            As[c4 * 4 + 2][row] = a.z;
            As[c4 * 4 + 3][row] = a.w;
        }
        // W tile: 16 k x 128 m
#pragma unroll
        for (int i = 0; i < 2; i++) {
            int idx = tid + i * 256;
            int row = idx >> 5, c4 = idx & 31;
            if (!GM) {
                *(float4*)&Bs[row][c4 * 4] =
                    *(const float4*)(W + (size_t)(k0 + row) * M + m0 + c4 * 4);
            } else {
#pragma unroll
                for (int j = 0; j < 4; j++) {
                    int m = m0 + c4 * 4 + j;
                    Bs[row][c4 * 4 + j] = (m < M) ? W[(size_t)(k0 + row) * M + m] : 0.f;
                }
            }
        }
        __syncthreads();
#pragma unroll
        for (int kk = 0; kk < 16; kk++) {
            float a[8], bb[8];
            *(float4*)&a[0]  = *(const float4*)&As[kk][ty * 8];
            *(float4*)&a[4]  = *(const float4*)&As[kk][ty * 8 + 4];
            *(float4*)&bb[0] = *(const float4*)&Bs[kk][tx * 8];
            *(float4*)&bb[4] = *(const float4*)&Bs[kk][tx * 8 + 4];
#pragma unroll
            for (int i = 0; i < 8; i++)
#pragma unroll
                for (int j = 0; j < 8; j++) acc[i][j] += a[i] * bb[j];
        }
        __syncthreads();
    }
    // epilogue
#pragma unroll
    for (int i = 0; i < 8; i++) {
        int n = n0 + ty * 8 + i;
#pragma unroll
        for (int j = 0; j < 8; j++) {
            int m = m0 + tx * 8 + j;
            if (GM && m >= M) continue;
            float vv = acc[i][j];
            if (bias) vv += bias[m];
            if (res)  vv += res[(size_t)n * M + m];
            if (relu) vv = fmaxf(vv, 0.f);
            C[(size_t)n * M + m] = vv;
        }
    }
}

// ---------------- causal attention: block per (b,h), thread per query -------
__global__ void __launch_bounds__(256) k_attn(
    const float* __restrict__ Q, const float* __restrict__ Kx,
    const float* __restrict__ Vx, float* __restrict__ O)
{
    __shared__ float Ks[64][64];
    __shared__ float Vs[64][64];
    const int h = blockIdx.x, b = blockIdx.y;
    const int tq = threadIdx.x;          // 0..255 == T
    const float scale = 0.125f;          // 1/sqrt(64)

    float4 q4[16], o4[16];
    const float4* qr = (const float4*)(Q + (size_t)(b * TT + tq) * EE + h * DD);
#pragma unroll
    for (int i = 0; i < 16; i++) { q4[i] = qr[i]; o4[i] = make_float4(0.f, 0.f, 0.f, 0.f); }
    float m = -INFINITY, l = 0.f;

    for (int c = 0; c < 4; c++) {
        // stage 64 K rows + 64 V rows of this head
#pragma unroll
        for (int i = 0; i < 4; i++) {
            int idx = threadIdx.x + i * 256;        // 1024 float4
            int r = idx >> 4, d4 = idx & 15;
            size_t goff = (size_t)(b * TT + c * 64 + r) * EE + h * DD;
            ((float4*)&Ks[r][0])[d4] = ((const float4*)(Kx + goff))[d4];
            ((float4*)&Vs[r][0])[d4] = ((const float4*)(Vx + goff))[d4];
        }
        __syncthreads();
        int rel = tq - c * 64;
        if (rel >= 0) {
            int kend = rel + 1; if (kend > 64) kend = 64;
            for (int kk = 0; kk < kend; kk++) {
                const float4* kr = (const float4*)&Ks[kk][0];
                float s = 0.f;
#pragma unroll
                for (int i = 0; i < 16; i++) {
                    float4 kv = kr[i];
                    s += q4[i].x * kv.x + q4[i].y * kv.y + q4[i].z * kv.z + q4[i].w * kv.w;
                }
                s *= scale;
                float mn = fmaxf(m, s);
                float p  = __expf(s - mn);
                float al = __expf(m - mn);
                l = l * al + p;
                const float4* vr = (const float4*)&Vs[kk][0];
#pragma unroll
                for (int i = 0; i < 16; i++) {
                    float4 vv = vr[i];
                    o4[i].x = o4[i].x * al + p * vv.x;
                    o4[i].y = o4[i].y * al + p * vv.y;
                    o4[i].z = o4[i].z * al + p * vv.z;
                    o4[i].w = o4[i].w * al + p * vv.w;
                }
                m = mn;
            }
        }
        __syncthreads();
    }
    float inv = 1.f / l;
    float4* orow = (float4*)(O + (size_t)(b * TT + tq) * EE + h * DD);
#pragma unroll
    for (int i = 0; i < 16; i++) {
        float4 o = o4[i];
        o.x *= inv; o.y *= inv; o.z *= inv; o.w *= inv;
        orow[i] = o;
    }
}

// ---------------- loss ------------------------------------------------------
__global__ void k_zero(float* loss) { *loss = 0.f; }

__global__ void k_loss(const float* __restrict__ logits, const int* __restrict__ tgt,
                       float* __restrict__ loss) {
    int warp = threadIdx.x >> 5, lane = threadIdx.x & 31;
    int row = blockIdx.x * 8 + warp;
    if (row >= NTOK) return;
    const float* lr = logits + (size_t)row * VV;
    float x0 = (lane < VV)      ? lr[lane]      : -INFINITY;
    float x1 = (lane + 32 < VV) ? lr[lane + 32] : -INFINITY;
    float x2 = (lane + 64 < VV) ? lr[lane + 64] : -INFINITY;
    float mx = fmaxf(x0, fmaxf(x1, x2));
#pragma unroll
    for (int off = 16; off > 0; off >>= 1) mx = fmaxf(mx, __shfl_xor_sync(0xffffffffu, mx, off));
    float se = 0.f;
    if (lane < VV)      se += expf(x0 - mx);
    if (lane + 32 < VV) se += expf(x1 - mx);
    if (lane + 64 < VV) se += expf(x2 - mx);
#pragma unroll
    for (int off = 16; off > 0; off >>= 1) se += __shfl_xor_sync(0xffffffffu, se, off);
    if (lane == 0) {
        float lt = lr[tgt[row]];
        atomicAdd(loss, mx + logf(se) - lt);
    }
}

__global__ void k_final(const float* __restrict__ loss, float* __restrict__ out) {
    out[0] = *loss * (1.f / NTOK);
}

// ---------------- host ------------------------------------------------------
extern "C" void kernel_launch(void* const* d_in, const int* in_sizes, int n_in,
                              void* d_out, int out_size) {
    const int*   idx  = (const int*)  d_in[0];
    const int*   tgt  = (const int*)  d_in[1];
    const float* tok  = (const float*)d_in[2];
    const float* pos  = (const float*)d_in[3];
    const float* Wq   = (const float*)d_in[4];
    const float* Wk   = (const float*)d_in[5];
    const float* Wv   = (const float*)d_in[6];
    const float* Wo   = (const float*)d_in[7];
    const float* bo   = (const float*)d_in[8];
    const float* W1   = (const float*)d_in[9];
    const float* b1   = (const float*)d_in[10];
    const float* W2   = (const float*)d_in[11];
    const float* b2w  = (const float*)d_in[12];
    const float* ln1g = (const float*)d_in[13];
    const float* ln1b = (const float*)d_in[14];
    const float* ln2g = (const float*)d_in[15];
    const float* ln2b = (const float*)d_in[16];
    const float* lnfg = (const float*)d_in[17];
    const float* lnfb = (const float*)d_in[18];
    const float* Wlm  = (const float*)d_in[19];
    const float* blm  = (const float*)d_in[20];

    float *x, *h, *q, *k, *v, *att, *f, *glog, *gloss;
    cudaGetSymbolAddress((void**)&x,    g_x);
    cudaGetSymbolAddress((void**)&h,    g_h);
    cudaGetSymbolAddress((void**)&q,    g_q);
    cudaGetSymbolAddress((void**)&k,    g_k);
    cudaGetSymbolAddress((void**)&v,    g_v);
    cudaGetSymbolAddress((void**)&att,  g_att);
    cudaGetSymbolAddress((void**)&f,    g_f);
    cudaGetSymbolAddress((void**)&glog, g_logits);
    cudaGetSymbolAddress((void**)&gloss, g_loss);

    float* outf   = (float*)d_out;
    float* logits = (out_size >= NTOK * VV) ? outf : glog;

    k_embed<<<(NTOK * EE + 255) / 256, 256>>>(idx, tok, pos, x);

    dim3 gE(EE / 128, NTOK / 128);   // (3,128)
    dim3 gF(FF / 128, NTOK / 128);   // (12,128)
    dim3 gLN(NTOK / 8);

    for (int l = 0; l < LLAY; l++) {
        const float* wq = Wq + (size_t)l * EE * EE;
        const float* wk = Wk + (size_t)l * EE * EE;
        const float* wv = Wv + (size_t)l * EE * EE;
        const float* wo = Wo + (size_t)l * EE * EE;
        const float* w1 = W1 + (size_t)l * EE * FF;
        const float* w2 = W2 + (size_t)l * FF * EE;

        k_ln<<<gLN, 256>>>(x, ln1g + l * EE, ln1b + l * EE, h);
        k_gemm<false><<<gE, 256>>>(h, wq, nullptr, nullptr, q, EE, EE, 0);
        k_gemm<false><<<gE, 256>>>(h, wk, nullptr, nullptr, k, EE, EE, 0);
        k_gemm<false><<<gE, 256>>>(h, wv, nullptr, nullptr, v, EE, EE, 0);
        k_attn<<<dim3(HH, BB), 256>>>(q, k, v, att);
        k_gemm<false><<<gE, 256>>>(att, wo, bo + l * EE, x, x, EE, EE, 0);
        k_ln<<<gLN, 256>>>(x, ln2g + l * EE, ln2b + l * EE, h);
        k_gemm<false><<<gF, 256>>>(h, w1, b1 + l * FF, nullptr, f, EE, FF, 1);
        k_gemm<false><<<gE, 256>>>(f, w2, b2w + l * EE, x, x, FF, EE, 0);
    }

    k_ln<<<gLN, 256>>>(x, lnfg, lnfb, h);
    k_gemm<true><<<dim3(1, NTOK / 128), 256>>>(h, Wlm, blm, nullptr, logits, EE, VV, 0);

    if (out_size == 1 || out_size > NTOK * VV) {
        k_zero<<<1, 1>>>(gloss);
        k_loss<<<NTOK / 8, 256>>>(logits, tgt, gloss);
        float* ldst = (out_size == 1) ? outf : (outf + NTOK * VV);
        k_final<<<1, 1>>>(gloss, ldst);
    }
}

// round 7
// speedup vs baseline: 1.0081x; 1.0081x over previous
#include <cuda_runtime.h>
#include <math.h>

// Problem constants
static const int BB = 64, TT = 256, VV = 65, EE = 384, HH = 6, LLAY = 6, DD = 64, FF = 1536;
static const int NTOK = BB * TT; // 16384

// ---------------- scratch (no allocation allowed -> device globals) ----------
__device__ __align__(16) float g_x  [16384 * 384];
__device__ __align__(16) float g_h  [16384 * 384];
__device__ __align__(16) float g_q  [16384 * 384];
__device__ __align__(16) float g_k  [16384 * 384];
__device__ __align__(16) float g_v  [16384 * 384];
__device__ __align__(16) float g_att[16384 * 384];
__device__ __align__(16) float g_f  [16384 * 1536];
__device__ __align__(16) float g_logits[16384 * 65];
__device__ __align__(16) float g_loss[1];

// ---------------- embedding ------------------------------------------------
__global__ void k_embed(const int* __restrict__ idx, const float* __restrict__ tok,
                        const float* __restrict__ pos, float* __restrict__ x) {
    int i = blockIdx.x * blockDim.x + threadIdx.x;
    if (i >= NTOK * EE) return;
    int n = i / EE, e = i - n * EE;
    int t = n % TT;
    x[i] = tok[idx[n] * EE + e] + pos[t * EE + e];
}

// ---------------- LayerNorm: warp per row ----------------------------------
__global__ void k_ln(const float* __restrict__ x, const float* __restrict__ g,
                     const float* __restrict__ b, float* __restrict__ y) {
    int warp = threadIdx.x >> 5, lane = threadIdx.x & 31;
    int row = blockIdx.x * 8 + warp;
    if (row >= NTOK) return;
    const float4* xr = (const float4*)(x + row * EE);
    float4 v[3];
#pragma unroll
    for (int i = 0; i < 3; i++) v[i] = xr[lane + i * 32];
    float s = 0.f, s2 = 0.f;
#pragma unroll
    for (int i = 0; i < 3; i++) {
        s  += v[i].x + v[i].y + v[i].z + v[i].w;
        s2 += v[i].x * v[i].x + v[i].y * v[i].y + v[i].z * v[i].z + v[i].w * v[i].w;
    }
#pragma unroll
    for (int off = 16; off > 0; off >>= 1) {
        s  += __shfl_xor_sync(0xffffffffu, s,  off);
        s2 += __shfl_xor_sync(0xffffffffu, s2, off);
    }
    float mu = s * (1.f / EE);
    float var = s2 * (1.f / EE) - mu * mu;
    float rs = rsqrtf(var + 1e-5f);
    float4* yr = (float4*)(y + row * EE);
    const float4* gr = (const float4*)g;
    const float4* br = (const float4*)b;
#pragma unroll
    for (int i = 0; i < 3; i++) {
        float4 gg = gr[lane + i * 32], bb = br[lane + i * 32];
        float4 o;
        o.x = (v[i].x - mu) * rs * gg.x + bb.x;
        o.y = (v[i].y - mu) * rs * gg.y + bb.y;
        o.z = (v[i].z - mu) * rs * gg.z + bb.z;
        o.w = (v[i].w - mu) * rs * gg.w + bb.w;
        yr[lane + i * 32] = o;
    }
}

// ---------------- tf32 -> 32-bit pattern helper ----------------------------
__device__ __forceinline__ float f2tf(float f) {
    unsigned u;
    asm("cvt.rna.tf32.f32 %0, %1;" : "=r"(u) : "f"(f));
    return __uint_as_float(u);
}

// ---------------- tensor-core GEMM: C[N,M] = A[N,K] @ W[K,M] ---------------
// 128x128x32 block tile, 8 warps (2x4), warp tile 64x32, m16n8k8 tf32 mma.
// Fragment-packed shared memory: global->smem scatter places each element at
// its mma-fragment position, so fragment loads are single LDS.128 / LDS.64.
// Requires K % 32 == 0, M % 128 == 0, N % 128 == 0.
__global__ void __launch_bounds__(256) k_gemm_tc(
    const float* __restrict__ A, const float* __restrict__ W,
    const float* __restrict__ bias, const float* __restrict__ res,
    float* __restrict__ C, int K, int M, int relu)
{
    extern __shared__ float smem[];
    float* As = smem;            // [2][4096]
    float* Bs = smem + 8192;     // [2][4096]

    const int n0 = blockIdx.y * 128;   // token rows
    const int m0 = blockIdx.x * 128;   // feature cols
    const int tid  = threadIdx.x;
    const int lane = tid & 31, warp = tid >> 5;
    const int wm = warp & 1, wn = warp >> 1;       // 2 x 4 warp grid
    const int gid = lane >> 2, tig = lane & 3;

    float acc[4][4][4];
#pragma unroll
    for (int a = 0; a < 4; a++)
#pragma unroll
        for (int b = 0; b < 4; b++)
#pragma unroll
            for (int c = 0; c < 4; c++) acc[a][b][c] = 0.f;

    const float* Ag = A + (size_t)n0 * K;
    const float* Wg = W + m0;
    const int KB = K >> 5;  // number of 32-wide K slabs

    float4 pa[4], pb[4];
    // initial global loads (slab 0)
#pragma unroll
    for (int i = 0; i < 4; i++) {
        int l = tid + i * 256;
        pa[i] = *(const float4*)(Ag + (size_t)(l >> 3) * K + ((l & 7) << 2));
        pb[i] = *(const float4*)(Wg + (size_t)(l >> 5) * M + ((l & 31) << 2));
    }
    // scatter slab 0 into buffer 0
    {
        float* as = As; float* bs = Bs;
#pragma unroll
        for (int i = 0; i < 4; i++) {
            int l = tid + i * 256;
            // A: row = l>>3 (0..127), c4 = l&7 (float4 index along k)
            int row = l >> 3, c4 = l & 7;
            int mt = row >> 4, ml = row & 15;
            int hm = ml >> 3, gA = ml & 7;
            int kt = c4 >> 1, hk = c4 & 1;
            int base = ((mt << 2) + kt) << 7;
            int reg = (hk << 1) + hm;
            const float* pv = (const float*)&pa[i];
#pragma unroll
            for (int j = 0; j < 4; j++)
                as[base + ((gA << 2) + j) * 4 + reg] = f2tf(pv[j]);
            // B: k = l>>5 (0..31), c4 = l&31 (float4 index along m)
            int k = l >> 5; c4 = l & 31;
            int bkt = k >> 3, kl = k & 7;
            int tB = kl & 3, hB = kl >> 2;
            int nt = c4 >> 1, gb = (c4 & 1) << 2;
            int bb = ((bkt << 4) + nt) << 6;
            const float* qv = (const float*)&pb[i];
#pragma unroll
            for (int j = 0; j < 4; j++)
                bs[bb + ((gb + j) * 4 + tB) * 2 + hB] = f2tf(qv[j]);
        }
    }
    __syncthreads();

    int p = 0;
    for (int kb = 0; kb < KB; kb++) {
        // prefetch next slab into registers
        if (kb + 1 < KB) {
            const float* Agn = Ag + ((kb + 1) << 5);
            const float* Wgn = Wg + (size_t)((kb + 1) << 5) * M;
#pragma unroll
            for (int i = 0; i < 4; i++) {
                int l = tid + i * 256;
                pa[i] = *(const float4*)(Agn + (size_t)(l >> 3) * K + ((l & 7) << 2));
                pb[i] = *(const float4*)(Wgn + (size_t)(l >> 5) * M + ((l & 31) << 2));
            }
        }
        // compute on buffer p
        const float* as = As + p * 4096;
        const float* bs = Bs + p * 4096;
#pragma unroll
        for (int kt = 0; kt < 4; kt++) {
            unsigned af[4][4];
            unsigned bf[4][2];
#pragma unroll
            for (int mi = 0; mi < 4; mi++) {
                int MT = (wm << 2) + mi;
                float4 v = *(const float4*)&as[(((MT << 2) + kt) << 7) + (lane << 2)];
                af[mi][0] = __float_as_uint(v.x); af[mi][1] = __float_as_uint(v.y);
                af[mi][2] = __float_as_uint(v.z); af[mi][3] = __float_as_uint(v.w);
            }
#pragma unroll
            for (int ni = 0; ni < 4; ni++) {
                int NT = (wn << 2) + ni;
                float2 v = *(const float2*)&bs[(((kt << 4) + NT) << 6) + (lane << 1)];
                bf[ni][0] = __float_as_uint(v.x); bf[ni][1] = __float_as_uint(v.y);
            }
#pragma unroll
            for (int mi = 0; mi < 4; mi++)
#pragma unroll
                for (int ni = 0; ni < 4; ni++) {
                    asm volatile(
                        "mma.sync.aligned.m16n8k8.row.col.f32.tf32.tf32.f32 "
                        "{%0,%1,%2,%3}, {%4,%5,%6,%7}, {%8,%9}, {%0,%1,%2,%3};"
                        : "+f"(acc[mi][ni][0]), "+f"(acc[mi][ni][1]),
                          "+f"(acc[mi][ni][2]), "+f"(acc[mi][ni][3])
                        : "r"(af[mi][0]), "r"(af[mi][1]), "r"(af[mi][2]), "r"(af[mi][3]),
                          "r"(bf[ni][0]), "r"(bf[ni][1]));
                }
        }
        // scatter prefetched slab into the other buffer
        if (kb + 1 < KB) {
            float* asn = As + (p ^ 1) * 4096;
            float* bsn = Bs + (p ^ 1) * 4096;
#pragma unroll
            for (int i = 0; i < 4; i++) {
                int l = tid + i * 256;
                int row = l >> 3, c4 = l & 7;
                int mt = row >> 4, ml = row & 15;
                int hm = ml >> 3, gA = ml & 7;
                int kt2 = c4 >> 1, hk = c4 & 1;
                int base = ((mt << 2) + kt2) << 7;
                int reg = (hk << 1) + hm;
                const float* pv = (const float*)&pa[i];
#pragma unroll
                for (int j = 0; j < 4; j++)
                    asn[base + ((gA << 2) + j) * 4 + reg] = f2tf(pv[j]);
                int k = l >> 5; c4 = l & 31;
                int bkt = k >> 3, kl = k & 7;
                int tB = kl & 3, hB = kl >> 2;
                int nt = c4 >> 1, gb = (c4 & 1) << 2;
                int bb = ((bkt << 4) + nt) << 6;
                const float* qv = (const float*)&pb[i];
#pragma unroll
                for (int j = 0; j < 4; j++)
                    bsn[bb + ((gb + j) * 4 + tB) * 2 + hB] = f2tf(qv[j]);
            }
            __syncthreads();
            p ^= 1;
        }
    }

    // epilogue: c0,c1 at (row, col..col+1), c2,c3 at (row+8, col..col+1)
#pragma unroll
    for (int mi = 0; mi < 4; mi++) {
        int row = n0 + (wm << 6) + (mi << 4) + gid;
#pragma unroll
        for (int ni = 0; ni < 4; ni++) {
            int col = m0 + (wn << 5) + (ni << 3) + (tig << 1);
            float b0 = 0.f, b1 = 0.f;
            if (bias) { b0 = bias[col]; b1 = bias[col + 1]; }
            float v0 = acc[mi][ni][0] + b0;
            float v1 = acc[mi][ni][1] + b1;
            float v2 = acc[mi][ni][2] + b0;
            float v3 = acc[mi][ni][3] + b1;
            if (res) {
                const float* r0 = res + (size_t)row * M + col;
                const float* r1 = res + (size_t)(row + 8) * M + col;
                v0 += r0[0]; v1 += r0[1]; v2 += r1[0]; v3 += r1[1];
            }
            if (relu) {
                v0 = fmaxf(v0, 0.f); v1 = fmaxf(v1, 0.f);
                v2 = fmaxf(v2, 0.f); v3 = fmaxf(v3, 0.f);
            }
            *(float2*)(C + (size_t)row * M + col)       = make_float2(v0, v1);
            *(float2*)(C + (size_t)(row + 8) * M + col) = make_float2(v2, v3);
        }
    }
}

// ---------------- fp32 GEMM (kept for LM head, M=65) -----------------------
__global__ void __launch_bounds__(256) k_gemm_pad(
    const float* __restrict__ A, const float* __restrict__ W,
    const float* __restrict__ bias, float* __restrict__ C, int K, int M)
{
    __shared__ float As[16][132];
    __shared__ float Bs[16][128];
    const int n0 = blockIdx.y * 128;
    const int m0 = 0;
    const int tid = threadIdx.x;
    const int tx = tid & 15, ty = tid >> 4;
    float acc[8][8];
#pragma unroll
    for (int i = 0; i < 8; i++)
#pragma unroll
        for (int j = 0; j < 8; j++) acc[i][j] = 0.f;

    for (int k0 = 0; k0 < K; k0 += 16) {
#pragma unroll
        for (int i = 0; i < 2; i++) {
            int idx = tid + i * 256;
            int row = idx >> 2, c4 = idx & 3;
            float4 a = *(const float4*)(A + (size_t)(n0 + row) * K + k0 + c4 * 4);
            As[c4 * 4 + 0][row] = a.x;
            As[c4 * 4 + 1][row] = a.y;
            As[c4 * 4 + 2][row] = a.z;
            As[c4 * 4 + 3][row] = a.w;
        }
#pragma unroll
        for (int i = 0; i < 2; i++) {
            int idx = tid + i * 256;
            int row = idx >> 5, c4 = idx & 31;
#pragma unroll
            for (int j = 0; j < 4; j++) {
                int m = m0 + c4 * 4 + j;
                Bs[row][c4 * 4 + j] = (m < M) ? W[(size_t)(k0 + row) * M + m] : 0.f;
            }
        }
        __syncthreads();
#pragma unroll
        for (int kk = 0; kk < 16; kk++) {
            float a[8], bb[8];
            *(float4*)&a[0]  = *(const float4*)&As[kk][ty * 8];
            *(float4*)&a[4]  = *(const float4*)&As[kk][ty * 8 + 4];
            *(float4*)&bb[0] = *(const float4*)&Bs[kk][tx * 8];
            *(float4*)&bb[4] = *(const float4*)&Bs[kk][tx * 8 + 4];
#pragma unroll
            for (int i = 0; i < 8; i++)
#pragma unroll
                for (int j = 0; j < 8; j++) acc[i][j] += a[i] * bb[j];
        }
        __syncthreads();
    }
#pragma unroll
    for (int i = 0; i < 8; i++) {
        int n = n0 + ty * 8 + i;
#pragma unroll
        for (int j = 0; j < 8; j++) {
            int m = m0 + tx * 8 + j;
            if (m >= M) continue;
            C[(size_t)n * M + m] = acc[i][j] + bias[m];
        }
    }
}

// ---------------- causal attention ------------------------------------------
__global__ void __launch_bounds__(256) k_attn(
    const float* __restrict__ Q, const float* __restrict__ Kx,
    const float* __restrict__ Vx, float* __restrict__ O)
{
    __shared__ float Ks[64][64];
    __shared__ float Vs[64][64];
    const int h = blockIdx.x, b = blockIdx.y;
    const int tq = threadIdx.x;
    const float scale = 0.125f;

    float4 q4[16], o4[16];
    const float4* qr = (const float4*)(Q + (size_t)(b * TT + tq) * EE + h * DD);
#pragma unroll
    for (int i = 0; i < 16; i++) { q4[i] = qr[i]; o4[i] = make_float4(0.f, 0.f, 0.f, 0.f); }
    float m = -INFINITY, l = 0.f;

    for (int c = 0; c < 4; c++) {
#pragma unroll
        for (int i = 0; i < 4; i++) {
            int idx = threadIdx.x + i * 256;
            int r = idx >> 4, d4 = idx & 15;
            size_t goff = (size_t)(b * TT + c * 64 + r) * EE + h * DD;
            ((float4*)&Ks[r][0])[d4] = ((const float4*)(Kx + goff))[d4];
            ((float4*)&Vs[r][0])[d4] = ((const float4*)(Vx + goff))[d4];
        }
        __syncthreads();
        int rel = tq - c * 64;
        if (rel >= 0) {
            int kend = rel + 1; if (kend > 64) kend = 64;
            for (int kk = 0; kk < kend; kk++) {
                const float4* kr = (const float4*)&Ks[kk][0];
                float s = 0.f;
#pragma unroll
                for (int i = 0; i < 16; i++) {
                    float4 kv = kr[i];
                    s += q4[i].x * kv.x + q4[i].y * kv.y + q4[i].z * kv.z + q4[i].w * kv.w;
                }
                s *= scale;
                float mn = fmaxf(m, s);
                float pp = __expf(s - mn);
                float al = __expf(m - mn);
                l = l * al + pp;
                const float4* vr = (const float4*)&Vs[kk][0];
#pragma unroll
                for (int i = 0; i < 16; i++) {
                    float4 vv = vr[i];
                    o4[i].x = o4[i].x * al + pp * vv.x;
                    o4[i].y = o4[i].y * al + pp * vv.y;
                    o4[i].z = o4[i].z * al + pp * vv.z;
                    o4[i].w = o4[i].w * al + pp * vv.w;
                }
                m = mn;
            }
        }
        __syncthreads();
    }
    float inv = 1.f / l;
    float4* orow = (float4*)(O + (size_t)(b * TT + tq) * EE + h * DD);
#pragma unroll
    for (int i = 0; i < 16; i++) {
        float4 o = o4[i];
        o.x *= inv; o.y *= inv; o.z *= inv; o.w *= inv;
        orow[i] = o;
    }
}

// ---------------- loss ------------------------------------------------------
__global__ void k_zero(float* loss) { *loss = 0.f; }

__global__ void k_loss(const float* __restrict__ logits, const int* __restrict__ tgt,
                       float* __restrict__ loss) {
    int warp = threadIdx.x >> 5, lane = threadIdx.x & 31;
    int row = blockIdx.x * 8 + warp;
    if (row >= NTOK) return;
    const float* lr = logits + (size_t)row * VV;
    float x0 = (lane < VV)      ? lr[lane]      : -INFINITY;
    float x1 = (lane + 32 < VV) ? lr[lane + 32] : -INFINITY;
    float x2 = (lane + 64 < VV) ? lr[lane + 64] : -INFINITY;
    float mx = fmaxf(x0, fmaxf(x1, x2));
#pragma unroll
    for (int off = 16; off > 0; off >>= 1) mx = fmaxf(mx, __shfl_xor_sync(0xffffffffu, mx, off));
    float se = 0.f;
    if (lane < VV)      se += expf(x0 - mx);
    if (lane + 32 < VV) se += expf(x1 - mx);
    if (lane + 64 < VV) se += expf(x2 - mx);
#pragma unroll
    for (int off = 16; off > 0; off >>= 1) se += __shfl_xor_sync(0xffffffffu, se, off);
    if (lane == 0) {
        float lt = lr[tgt[row]];
        atomicAdd(loss, mx + logf(se) - lt);
    }
}

__global__ void k_final(const float* __restrict__ loss, float* __restrict__ out) {
    out[0] = *loss * (1.f / NTOK);
}

// ---------------- host ------------------------------------------------------
extern "C" void kernel_launch(void* const* d_in, const int* in_sizes, int n_in,
                              void* d_out, int out_size) {
    const int*   idx  = (const int*)  d_in[0];
    const int*   tgt  = (const int*)  d_in[1];
    const float* tok  = (const float*)d_in[2];
    const float* pos  = (const float*)d_in[3];
    const float* Wq   = (const float*)d_in[4];
    const float* Wk   = (const float*)d_in[5];
    const float* Wv   = (const float*)d_in[6];
    const float* Wo   = (const float*)d_in[7];
    const float* bo   = (const float*)d_in[8];
    const float* W1   = (const float*)d_in[9];
    const float* b1   = (const float*)d_in[10];
    const float* W2   = (const float*)d_in[11];
    const float* b2w  = (const float*)d_in[12];
    const float* ln1g = (const float*)d_in[13];
    const float* ln1b = (const float*)d_in[14];
    const float* ln2g = (const float*)d_in[15];
    const float* ln2b = (const float*)d_in[16];
    const float* lnfg = (const float*)d_in[17];
    const float* lnfb = (const float*)d_in[18];
    const float* Wlm  = (const float*)d_in[19];
    const float* blm  = (const float*)d_in[20];

    float *x, *h, *q, *k, *v, *att, *f, *glog, *gloss;
    cudaGetSymbolAddress((void**)&x,    g_x);
    cudaGetSymbolAddress((void**)&h,    g_h);
    cudaGetSymbolAddress((void**)&q,    g_q);
    cudaGetSymbolAddress((void**)&k,    g_k);
    cudaGetSymbolAddress((void**)&v,    g_v);
    cudaGetSymbolAddress((void**)&att,  g_att);
    cudaGetSymbolAddress((void**)&f,    g_f);
    cudaGetSymbolAddress((void**)&glog, g_logits);
    cudaGetSymbolAddress((void**)&gloss, g_loss);

    static int smem_set = 0;
    if (!smem_set) {
        cudaFuncSetAttribute(k_gemm_tc, cudaFuncAttributeMaxDynamicSharedMemorySize, 65536);
        smem_set = 1;
    }

    float* outf   = (float*)d_out;
    float* logits = (out_size >= NTOK * VV) ? outf : glog;

    k_embed<<<(NTOK * EE + 255) / 256, 256>>>(idx, tok, pos, x);

    dim3 gE(EE / 128, NTOK / 128);   // (3,128)
    dim3 gF(FF / 128, NTOK / 128);   // (12,128)
    dim3 gLN(NTOK / 8);
    const int DSM = 65536;

    for (int l = 0; l < LLAY; l++) {
        const float* wq = Wq + (size_t)l * EE * EE;
        const float* wk = Wk + (size_t)l * EE * EE;
        const float* wv = Wv + (size_t)l * EE * EE;
        const float* wo = Wo + (size_t)l * EE * EE;
        const float* w1 = W1 + (size_t)l * EE * FF;
        const float* w2 = W2 + (size_t)l * FF * EE;

        k_ln<<<gLN, 256>>>(x, ln1g + l * EE, ln1b + l * EE, h);
        k_gemm_tc<<<gE, 256, DSM>>>(h, wq, nullptr, nullptr, q, EE, EE, 0);
        k_gemm_tc<<<gE, 256, DSM>>>(h, wk, nullptr, nullptr, k, EE, EE, 0);
        k_gemm_tc<<<gE, 256, DSM>>>(h, wv, nullptr, nullptr, v, EE, EE, 0);
        k_attn<<<dim3(HH, BB), 256>>>(q, k, v, att);
        k_gemm_tc<<<gE, 256, DSM>>>(att, wo, bo + l * EE, x, x, EE, EE, 0);
        k_ln<<<gLN, 256>>>(x, ln2g + l * EE, ln2b + l * EE, h);
        k_gemm_tc<<<gF, 256, DSM>>>(h, w1, b1 + l * FF, nullptr, f, EE, FF, 1);
        k_gemm_tc<<<gE, 256, DSM>>>(f, w2, b2w + l * EE, x, x, FF, EE, 0);
    }

    k_ln<<<gLN, 256>>>(x, lnfg, lnfb, h);
    k_gemm_pad<<<dim3(1, NTOK / 128), 256>>>(h, Wlm, blm, logits, EE, VV);

    if (out_size == 1 || out_size > NTOK * VV) {
        k_zero<<<1, 1>>>(gloss);
        k_loss<<<NTOK / 8, 256>>>(logits, tgt, gloss);
        float* ldst = (out_size == 1) ? outf : (outf + NTOK * VV);
        k_final<<<1, 1>>>(gloss, ldst);
    }
}

// round 8
// speedup vs baseline: 2.7272x; 2.7054x over previous
#include <cuda_runtime.h>
#include <math.h>

// Problem constants
static const int BB = 64, TT = 256, VV = 65, EE = 384, HH = 6, LLAY = 6, DD = 64, FF = 1536;
static const int NTOK = BB * TT; // 16384

// ---------------- scratch ----------------------------------------------------
__device__ __align__(16) float g_x  [16384 * 384];
__device__ __align__(16) float g_h  [16384 * 384];   // packed (or natural for final LN)
__device__ __align__(16) float g_q  [16384 * 384];
__device__ __align__(16) float g_k  [16384 * 384];
__device__ __align__(16) float g_v  [16384 * 384];
__device__ __align__(16) float g_att[16384 * 384];   // packed
__device__ __align__(16) float g_f  [16384 * 1536];  // packed
__device__ __align__(16) float g_logits[16384 * 65];
__device__ __align__(16) float g_loss[1];
// packed tf32 weights: qkvo (4*L*E*E) + w1 (L*E*F) + w2 (L*F*E)
__device__ __align__(16) float g_pw [4 * 6 * 384 * 384 + 2 * 6 * 384 * 1536];

// ---------------- helpers ----------------------------------------------------
__device__ __forceinline__ float f2tf(float f) {
    unsigned u;
    asm("cvt.rna.tf32.f32 %0, %1;" : "=r"(u) : "f"(f));
    return __uint_as_float(u);
}
// packed-A index for element (row, col) of an [N x Kc] activation matrix
__device__ __forceinline__ int pk_a(int row, int col, int Kc) {
    return ((row >> 4) * (Kc >> 3) + (col >> 3)) * 128
         + ((row & 7) * 4 + (col & 3)) * 4 + ((row >> 3) & 1) + ((col >> 2) & 1) * 2;
}
// packed-B index for element (k, m) of a [K x M] weight matrix
__device__ __forceinline__ int pk_b(int k, int m, int M) {
    return ((k >> 3) * (M >> 3) + (m >> 3)) * 64
         + ((m & 7) * 4 + (k & 3)) * 2 + ((k >> 2) & 1);
}
__device__ __forceinline__ void cpa16(unsigned s, const float* g) {
    asm volatile("cp.async.cg.shared.global [%0], [%1], 16;" :: "r"(s), "l"(g));
}

// ---------------- weight pre-pack (once per launch, per weight group) --------
__global__ void k_packW(const float* __restrict__ W, float* __restrict__ PW,
                        int K, int M) {
    int i = blockIdx.x * blockDim.x + threadIdx.x;
    int tot = K * M;
    if (i >= tot) return;
    const float* w = W + (size_t)blockIdx.y * tot;
    float* pw = PW + (size_t)blockIdx.y * tot;
    int k = i / M, m = i - k * M;
    pw[pk_b(k, m, M)] = f2tf(w[i]);
}

// ---------------- embedding --------------------------------------------------
__global__ void k_embed(const int* __restrict__ idx, const float* __restrict__ tok,
                        const float* __restrict__ pos, float* __restrict__ x) {
    int i = blockIdx.x * blockDim.x + threadIdx.x;
    if (i >= NTOK * EE) return;
    int n = i / EE, e = i - n * EE;
    int t = n % TT;
    x[i] = tok[idx[n] * EE + e] + pos[t * EE + e];
}

// ---------------- LayerNorm (natural in, packed or natural out) --------------
__global__ void k_ln(const float* __restrict__ x, const float* __restrict__ g,
                     const float* __restrict__ b, float* __restrict__ y, int packed) {
    int warp = threadIdx.x >> 5, lane = threadIdx.x & 31;
    int row = blockIdx.x * 8 + warp;
    if (row >= NTOK) return;
    const float4* xr = (const float4*)(x + (size_t)row * EE);
    float4 v[3];
#pragma unroll
    for (int i = 0; i < 3; i++) v[i] = xr[lane + i * 32];
    float s = 0.f, s2 = 0.f;
#pragma unroll
    for (int i = 0; i < 3; i++) {
        s  += v[i].x + v[i].y + v[i].z + v[i].w;
        s2 += v[i].x * v[i].x + v[i].y * v[i].y + v[i].z * v[i].z + v[i].w * v[i].w;
    }
#pragma unroll
    for (int off = 16; off > 0; off >>= 1) {
        s  += __shfl_xor_sync(0xffffffffu, s,  off);
        s2 += __shfl_xor_sync(0xffffffffu, s2, off);
    }
    float mu = s * (1.f / EE);
    float var = s2 * (1.f / EE) - mu * mu;
    float rs = rsqrtf(var + 1e-5f);
    const float4* gr = (const float4*)g;
    const float4* br = (const float4*)b;
    if (packed) {
#pragma unroll
        for (int i = 0; i < 3; i++) {
            float4 gg = gr[lane + i * 32], bb = br[lane + i * 32];
            float o0 = (v[i].x - mu) * rs * gg.x + bb.x;
            float o1 = (v[i].y - mu) * rs * gg.y + bb.y;
            float o2 = (v[i].z - mu) * rs * gg.z + bb.z;
            float o3 = (v[i].w - mu) * rs * gg.w + bb.w;
            int cb = (lane + i * 32) * 4;
            y[pk_a(row, cb + 0, EE)] = f2tf(o0);
            y[pk_a(row, cb + 1, EE)] = f2tf(o1);
            y[pk_a(row, cb + 2, EE)] = f2tf(o2);
            y[pk_a(row, cb + 3, EE)] = f2tf(o3);
        }
    } else {
        float4* yr = (float4*)(y + (size_t)row * EE);
#pragma unroll
        for (int i = 0; i < 3; i++) {
            float4 gg = gr[lane + i * 32], bb = br[lane + i * 32];
            float4 o;
            o.x = (v[i].x - mu) * rs * gg.x + bb.x;
            o.y = (v[i].y - mu) * rs * gg.y + bb.y;
            o.z = (v[i].z - mu) * rs * gg.z + bb.z;
            o.w = (v[i].w - mu) * rs * gg.w + bb.w;
            yr[lane + i * 32] = o;
        }
    }
}

// ---------------- tf32 tensor-core GEMM, packed inputs -----------------------
// C[N,M] = A[N,K] @ W[K,M]; A,W pre-packed tf32 fragment layout in global.
// 128x128x32 block tile, 8 warps (2x4), warp tile 64x32, m16n8k8 mma.
// 3-stage cp.async pipeline. flags: 1=relu, 2=packed output.
__global__ void __launch_bounds__(256, 2) k_gemm_tc2(
    const float* __restrict__ PA, const float* __restrict__ PB,
    const float* __restrict__ bias, const float* __restrict__ res,
    float* __restrict__ C, int K, int M, int flags)
{
    extern __shared__ float smem[];   // 3 stages x (A 4096 + B 4096) floats
    const int n0 = blockIdx.y * 128;
    const int m0 = blockIdx.x * 128;
    const int tid  = threadIdx.x;
    const int lane = tid & 31, warp = tid >> 5;
    const int wm = warp & 1, wn = warp >> 1;
    const int gid = lane >> 2, tig = lane & 3;
    const int K8 = K >> 3, M8 = M >> 3;
    const int KB = K >> 5;

    // per-thread cp.async sources (advance by slab stride each stage)
    const float* gA[4]; const float* gB[4];
    unsigned sA[4], sB[4];
#pragma unroll
    for (int i = 0; i < 4; i++) {
        int ch = tid + i * 256;
        int mt = ch >> 7, kt = (ch >> 5) & 3, c4 = ch & 31;
        sA[i] = (unsigned)(((mt * 4 + kt) * 128 + c4 * 4) * 4);
        gA[i] = PA + ((size_t)((n0 >> 4) + mt) * K8 + kt) * 128 + c4 * 4;
        int bkt = ch >> 8, nt = (ch >> 4) & 15, d4 = ch & 15;
        sB[i] = (unsigned)((4096 + (bkt * 16 + nt) * 64 + d4 * 4) * 4);
        gB[i] = PB + ((size_t)bkt * M8 + (m0 >> 3) + nt) * 64 + d4 * 4;
    }
    const int strA = 512;        // floats per 32-K slab
    const int strB = 32 * M;

    unsigned smem_u = (unsigned)__cvta_generic_to_shared(smem);

    auto issue = [&](int ks, int buf) {
        unsigned base = smem_u + (unsigned)buf * 8192u * 4u;
#pragma unroll
        for (int i = 0; i < 4; i++) cpa16(base + sA[i], gA[i] + (size_t)ks * strA);
#pragma unroll
        for (int i = 0; i < 4; i++) cpa16(base + sB[i], gB[i] + (size_t)ks * strB);
    };

    float acc[4][4][4];
#pragma unroll
    for (int a = 0; a < 4; a++)
#pragma unroll
        for (int b = 0; b < 4; b++)
#pragma unroll
            for (int c = 0; c < 4; c++) acc[a][b][c] = 0.f;

    issue(0, 0);
    asm volatile("cp.async.commit_group;" ::: "memory");
    issue(1, 1);
    asm volatile("cp.async.commit_group;" ::: "memory");

    int p = 0;
    for (int kb = 0; kb < KB; kb++) {
        asm volatile("cp.async.wait_group 1;" ::: "memory");
        __syncthreads();
        if (kb + 2 < KB) issue(kb + 2, (kb + 2) % 3);
        asm volatile("cp.async.commit_group;" ::: "memory");

        const float* as = smem + p * 8192;
        const float* bs = as + 4096;
#pragma unroll
        for (int kt = 0; kt < 4; kt++) {
            unsigned af[4][4], bf[4][2];
#pragma unroll
            for (int mi = 0; mi < 4; mi++) {
                float4 v = *(const float4*)&as[((((wm * 4 + mi) * 4) + kt) << 7) + (lane << 2)];
                af[mi][0] = __float_as_uint(v.x); af[mi][1] = __float_as_uint(v.y);
                af[mi][2] = __float_as_uint(v.z); af[mi][3] = __float_as_uint(v.w);
            }
#pragma unroll
            for (int ni = 0; ni < 4; ni++) {
                float2 v = *(const float2*)&bs[(((kt * 16) + (wn * 4 + ni)) << 6) + (lane << 1)];
                bf[ni][0] = __float_as_uint(v.x); bf[ni][1] = __float_as_uint(v.y);
            }
#pragma unroll
            for (int mi = 0; mi < 4; mi++)
#pragma unroll
                for (int ni = 0; ni < 4; ni++) {
                    asm volatile(
                        "mma.sync.aligned.m16n8k8.row.col.f32.tf32.tf32.f32 "
                        "{%0,%1,%2,%3}, {%4,%5,%6,%7}, {%8,%9}, {%0,%1,%2,%3};"
                        : "+f"(acc[mi][ni][0]), "+f"(acc[mi][ni][1]),
                          "+f"(acc[mi][ni][2]), "+f"(acc[mi][ni][3])
                        : "r"(af[mi][0]), "r"(af[mi][1]), "r"(af[mi][2]), "r"(af[mi][3]),
                          "r"(bf[ni][0]), "r"(bf[ni][1]));
                }
        }
        p = (p == 2) ? 0 : p + 1;
    }

    const bool relu = (flags & 1), pko = (flags & 2);
#pragma unroll
    for (int mi = 0; mi < 4; mi++) {
        int row = n0 + (wm << 6) + (mi << 4) + gid;
#pragma unroll
        for (int ni = 0; ni < 4; ni++) {
            int col = m0 + (wn << 5) + (ni << 3) + (tig << 1);
            float b0 = 0.f, b1 = 0.f;
            if (bias) { b0 = bias[col]; b1 = bias[col + 1]; }
            float v0 = acc[mi][ni][0] + b0;
            float v1 = acc[mi][ni][1] + b1;
            float v2 = acc[mi][ni][2] + b0;
            float v3 = acc[mi][ni][3] + b1;
            if (res) {
                const float* r0 = res + (size_t)row * M + col;
                const float* r1 = res + (size_t)(row + 8) * M + col;
                v0 += r0[0]; v1 += r0[1]; v2 += r1[0]; v3 += r1[1];
            }
            if (relu) {
                v0 = fmaxf(v0, 0.f); v1 = fmaxf(v1, 0.f);
                v2 = fmaxf(v2, 0.f); v3 = fmaxf(v3, 0.f);
            }
            if (pko) {
                C[pk_a(row,     col,     M)] = f2tf(v0);
                C[pk_a(row,     col + 1, M)] = f2tf(v1);
                C[pk_a(row + 8, col,     M)] = f2tf(v2);
                C[pk_a(row + 8, col + 1, M)] = f2tf(v3);
            } else {
                *(float2*)(C + (size_t)row * M + col)       = make_float2(v0, v1);
                *(float2*)(C + (size_t)(row + 8) * M + col) = make_float2(v2, v3);
            }
        }
    }
}

// ---------------- fp32 GEMM for LM head (M=65, natural h) --------------------
__global__ void __launch_bounds__(256) k_gemm_pad(
    const float* __restrict__ A, const float* __restrict__ W,
    const float* __restrict__ bias, float* __restrict__ C, int K, int M)
{
    __shared__ float As[16][132];
    __shared__ float Bs[16][128];
    const int n0 = blockIdx.y * 128;
    const int tid = threadIdx.x;
    const int tx = tid & 15, ty = tid >> 4;
    float acc[8][8];
#pragma unroll
    for (int i = 0; i < 8; i++)
#pragma unroll
        for (int j = 0; j < 8; j++) acc[i][j] = 0.f;

    for (int k0 = 0; k0 < K; k0 += 16) {
#pragma unroll
        for (int i = 0; i < 2; i++) {
            int idx = tid + i * 256;
            int row = idx >> 2, c4 = idx & 3;
            float4 a = *(const float4*)(A + (size_t)(n0 + row) * K + k0 + c4 * 4);
            As[c4 * 4 + 0][row] = a.x;
            As[c4 * 4 + 1][row] = a.y;
            As[c4 * 4 + 2][row] = a.z;
            As[c4 * 4 + 3][row] = a.w;
        }
#pragma unroll
        for (int i = 0; i < 2; i++) {
            int idx = tid + i * 256;
            int row = idx >> 5, c4 = idx & 31;
#pragma unroll
            for (int j = 0; j < 4; j++) {
                int m = c4 * 4 + j;
                Bs[row][c4 * 4 + j] = (m < M) ? W[(size_t)(k0 + row) * M + m] : 0.f;
            }
        }
        __syncthreads();
#pragma unroll
        for (int kk = 0; kk < 16; kk++) {
            float a[8], bb[8];
            *(float4*)&a[0]  = *(const float4*)&As[kk][ty * 8];
            *(float4*)&a[4]  = *(const float4*)&As[kk][ty * 8 + 4];
            *(float4*)&bb[0] = *(const float4*)&Bs[kk][tx * 8];
            *(float4*)&bb[4] = *(const float4*)&Bs[kk][tx * 8 + 4];
#pragma unroll
            for (int i = 0; i < 8; i++)
#pragma unroll
                for (int j = 0; j < 8; j++) acc[i][j] += a[i] * bb[j];
        }
        __syncthreads();
    }
#pragma unroll
    for (int i = 0; i < 8; i++) {
        int n = n0 + ty * 8 + i;
#pragma unroll
        for (int j = 0; j < 8; j++) {
            int m = tx * 8 + j;
            if (m >= M) continue;
            C[(size_t)n * M + m] = acc[i][j] + bias[m];
        }
    }
}

// ---------------- causal attention (natural q/k/v in, packed att out) --------
__global__ void __launch_bounds__(256) k_attn(
    const float* __restrict__ Q, const float* __restrict__ Kx,
    const float* __restrict__ Vx, float* __restrict__ O)
{
    __shared__ float Ks[64][64];
    __shared__ float Vs[64][64];
    const int hd = blockIdx.x, b = blockIdx.y;
    const int tq = threadIdx.x;
    const float scale = 0.125f;

    float4 q4[16], o4[16];
    const float4* qr = (const float4*)(Q + (size_t)(b * TT + tq) * EE + hd * DD);
#pragma unroll
    for (int i = 0; i < 16; i++) { q4[i] = qr[i]; o4[i] = make_float4(0.f, 0.f, 0.f, 0.f); }
    float m = -INFINITY, l = 0.f;

    for (int c = 0; c < 4; c++) {
#pragma unroll
        for (int i = 0; i < 4; i++) {
            int idx = threadIdx.x + i * 256;
            int r = idx >> 4, d4 = idx & 15;
            size_t goff = (size_t)(b * TT + c * 64 + r) * EE + hd * DD;
            ((float4*)&Ks[r][0])[d4] = ((const float4*)(Kx + goff))[d4];
            ((float4*)&Vs[r][0])[d4] = ((const float4*)(Vx + goff))[d4];
        }
        __syncthreads();
        int rel = tq - c * 64;
        if (rel >= 0) {
            int kend = rel + 1; if (kend > 64) kend = 64;
            for (int kk = 0; kk < kend; kk++) {
                const float4* kr = (const float4*)&Ks[kk][0];
                float s = 0.f;
#pragma unroll
                for (int i = 0; i < 16; i++) {
                    float4 kv = kr[i];
                    s += q4[i].x * kv.x + q4[i].y * kv.y + q4[i].z * kv.z + q4[i].w * kv.w;
                }
                s *= scale;
                float mn = fmaxf(m, s);
                float pp = __expf(s - mn);
                float al = __expf(m - mn);
                l = l * al + pp;
                const float4* vr = (const float4*)&Vs[kk][0];
#pragma unroll
                for (int i = 0; i < 16; i++) {
                    float4 vv = vr[i];
                    o4[i].x = o4[i].x * al + pp * vv.x;
                    o4[i].y = o4[i].y * al + pp * vv.y;
                    o4[i].z = o4[i].z * al + pp * vv.z;
                    o4[i].w = o4[i].w * al + pp * vv.w;
                }
                m = mn;
            }
        }
        __syncthreads();
    }
    float inv = 1.f / l;
    int rowR = b * TT + tq;
#pragma unroll
    for (int i = 0; i < 16; i++) {
        int cb = hd * DD + i * 4;
        O[pk_a(rowR, cb + 0, EE)] = f2tf(o4[i].x * inv);
        O[pk_a(rowR, cb + 1, EE)] = f2tf(o4[i].y * inv);
        O[pk_a(rowR, cb + 2, EE)] = f2tf(o4[i].z * inv);
        O[pk_a(rowR, cb + 3, EE)] = f2tf(o4[i].w * inv);
    }
}

// ---------------- loss -------------------------------------------------------
__global__ void k_zero(float* loss) { *loss = 0.f; }

__global__ void k_loss(const float* __restrict__ logits, const int* __restrict__ tgt,
                       float* __restrict__ loss) {
    int warp = threadIdx.x >> 5, lane = threadIdx.x & 31;
    int row = blockIdx.x * 8 + warp;
    if (row >= NTOK) return;
    const float* lr = logits + (size_t)row * VV;
    float x0 = (lane < VV)      ? lr[lane]      : -INFINITY;
    float x1 = (lane + 32 < VV) ? lr[lane + 32] : -INFINITY;
    float x2 = (lane + 64 < VV) ? lr[lane + 64] : -INFINITY;
    float mx = fmaxf(x0, fmaxf(x1, x2));
#pragma unroll
    for (int off = 16; off > 0; off >>= 1) mx = fmaxf(mx, __shfl_xor_sync(0xffffffffu, mx, off));
    float se = 0.f;
    if (lane < VV)      se += expf(x0 - mx);
    if (lane + 32 < VV) se += expf(x1 - mx);
    if (lane + 64 < VV) se += expf(x2 - mx);
#pragma unroll
    for (int off = 16; off > 0; off >>= 1) se += __shfl_xor_sync(0xffffffffu, se, off);
    if (lane == 0) {
        float lt = lr[tgt[row]];
        atomicAdd(loss, mx + logf(se) - lt);
    }
}

__global__ void k_final(const float* __restrict__ loss, float* __restrict__ out) {
    out[0] = *loss * (1.f / NTOK);
}

// ---------------- host -------------------------------------------------------
extern "C" void kernel_launch(void* const* d_in, const int* in_sizes, int n_in,
                              void* d_out, int out_size) {
    const int*   idx  = (const int*)  d_in[0];
    const int*   tgt  = (const int*)  d_in[1];
    const float* tok  = (const float*)d_in[2];
    const float* pos  = (const float*)d_in[3];
    const float* Wq   = (const float*)d_in[4];
    const float* Wk   = (const float*)d_in[5];
    const float* Wv   = (const float*)d_in[6];
    const float* Wo   = (const float*)d_in[7];
    const float* bo   = (const float*)d_in[8];
    const float* W1   = (const float*)d_in[9];
    const float* b1   = (const float*)d_in[10];
    const float* W2   = (const float*)d_in[11];
    const float* b2w  = (const float*)d_in[12];
    const float* ln1g = (const float*)d_in[13];
    const float* ln1b = (const float*)d_in[14];
    const float* ln2g = (const float*)d_in[15];
    const float* ln2b = (const float*)d_in[16];
    const float* lnfg = (const float*)d_in[17];
    const float* lnfb = (const float*)d_in[18];
    const float* Wlm  = (const float*)d_in[19];
    const float* blm  = (const float*)d_in[20];

    float *x, *h, *q, *k, *v, *att, *f, *glog, *gloss, *pw;
    cudaGetSymbolAddress((void**)&x,    g_x);
    cudaGetSymbolAddress((void**)&h,    g_h);
    cudaGetSymbolAddress((void**)&q,    g_q);
    cudaGetSymbolAddress((void**)&k,    g_k);
    cudaGetSymbolAddress((void**)&v,    g_v);
    cudaGetSymbolAddress((void**)&att,  g_att);
    cudaGetSymbolAddress((void**)&f,    g_f);
    cudaGetSymbolAddress((void**)&glog, g_logits);
    cudaGetSymbolAddress((void**)&gloss, g_loss);
    cudaGetSymbolAddress((void**)&pw,   g_pw);

    static int smem_set = 0;
    if (!smem_set) {
        cudaFuncSetAttribute(k_gemm_tc2, cudaFuncAttributeMaxDynamicSharedMemorySize, 98304);
        smem_set = 1;
    }

    const int EExEE = EE * EE, EExFF = EE * FF;
    float* pwq = pw;
    float* pwk = pwq + (size_t)LLAY * EExEE;
    float* pwv = pwk + (size_t)LLAY * EExEE;
    float* pwo = pwv + (size_t)LLAY * EExEE;
    float* pw1 = pwo + (size_t)LLAY * EExEE;
    float* pw2 = pw1 + (size_t)LLAY * EExFF;

    // pre-pack all weights to tf32 fragment layout (bandwidth-trivial)
    k_packW<<<dim3((EExEE + 255) / 256, LLAY), 256>>>(Wq, pwq, EE, EE);
    k_packW<<<dim3((EExEE + 255) / 256, LLAY), 256>>>(Wk, pwk, EE, EE);
    k_packW<<<dim3((EExEE + 255) / 256, LLAY), 256>>>(Wv, pwv, EE, EE);
    k_packW<<<dim3((EExEE + 255) / 256, LLAY), 256>>>(Wo, pwo, EE, EE);
    k_packW<<<dim3((EExFF + 255) / 256, LLAY), 256>>>(W1, pw1, EE, FF);
    k_packW<<<dim3((EExFF + 255) / 256, LLAY), 256>>>(W2, pw2, FF, EE);

    float* outf   = (float*)d_out;
    float* logits = (out_size >= NTOK * VV) ? outf : glog;

    k_embed<<<(NTOK * EE + 255) / 256, 256>>>(idx, tok, pos, x);

    dim3 gE(EE / 128, NTOK / 128);   // (3,128)
    dim3 gF(FF / 128, NTOK / 128);   // (12,128)
    dim3 gLN(NTOK / 8);
    const int DSM = 98304;

    for (int l = 0; l < LLAY; l++) {
        k_ln<<<gLN, 256>>>(x, ln1g + l * EE, ln1b + l * EE, h, 1);
        k_gemm_tc2<<<gE, 256, DSM>>>(h, pwq + (size_t)l * EExEE, nullptr, nullptr, q, EE, EE, 0);
        k_gemm_tc2<<<gE, 256, DSM>>>(h, pwk + (size_t)l * EExEE, nullptr, nullptr, k, EE, EE, 0);
        k_gemm_tc2<<<gE, 256, DSM>>>(h, pwv + (size_t)l * EExEE, nullptr, nullptr, v, EE, EE, 0);
        k_attn<<<dim3(HH, BB), 256>>>(q, k, v, att);
        k_gemm_tc2<<<gE, 256, DSM>>>(att, pwo + (size_t)l * EExEE, bo + l * EE, x, x, EE, EE, 0);
        k_ln<<<gLN, 256>>>(x, ln2g + l * EE, ln2b + l * EE, h, 1);
        k_gemm_tc2<<<gF, 256, DSM>>>(h, pw1 + (size_t)l * EExFF, b1 + l * FF, nullptr, f, EE, FF, 1 | 2);
        k_gemm_tc2<<<gE, 256, DSM>>>(f, pw2 + (size_t)l * EExFF, b2w + l * EE, x, x, FF, EE, 0);
    }

    k_ln<<<gLN, 256>>>(x, lnfg, lnfb, h, 0);
    k_gemm_pad<<<dim3(1, NTOK / 128), 256>>>(h, Wlm, blm, logits, EE, VV);

    if (out_size == 1 || out_size > NTOK * VV) {
        k_zero<<<1, 1>>>(gloss);
        k_loss<<<NTOK / 8, 256>>>(logits, tgt, gloss);
        float* ldst = (out_size == 1) ? outf : (outf + NTOK * VV);
        k_final<<<1, 1>>>(gloss, ldst);
    }
}

// round 9
// speedup vs baseline: 2.8845x; 1.0577x over previous
#include <cuda_runtime.h>
#include <math.h>

// Problem constants
static const int BB = 64, TT = 256, VV = 65, EE = 384, HH = 6, LLAY = 6, DD = 64, FF = 1536;
static const int NTOK = BB * TT; // 16384
static const int QKVM = 3 * EE;  // 1152

// ---------------- scratch ----------------------------------------------------
__device__ __align__(16) float g_x  [16384 * 384];
__device__ __align__(16) float g_h  [16384 * 384];    // packed LN output
__device__ __align__(16) float g_qkv[16384 * 1152];   // natural, stride 1152
__device__ __align__(16) float g_att[16384 * 384];    // packed
__device__ __align__(16) float g_f  [16384 * 1536];   // packed FFN / head scratch
__device__ __align__(16) float g_logits[16384 * 65];
__device__ __align__(16) float g_loss[1];
// packed tf32 weights: qkv (L*E*3E) + wo (L*E*E) + w1 (L*E*F) + w2 (L*F*E) + wlm (E*128)
__device__ __align__(16) float g_pw[10665984];

// ---------------- helpers ----------------------------------------------------
__device__ __forceinline__ float f2tf(float f) {
    unsigned u;
    asm("cvt.rna.tf32.f32 %0, %1;" : "=r"(u) : "f"(f));
    return __uint_as_float(u);
}
__device__ __forceinline__ int pk_a(int row, int col, int Kc) {
    return ((row >> 4) * (Kc >> 3) + (col >> 3)) * 128
         + ((row & 7) * 4 + (col & 3)) * 4 + ((row >> 3) & 1) + ((col >> 2) & 1) * 2;
}
__device__ __forceinline__ int pk_b(int k, int m, int M) {
    return ((k >> 3) * (M >> 3) + (m >> 3)) * 64
         + ((m & 7) * 4 + (k & 3)) * 2 + ((k >> 2) & 1);
}
__device__ __forceinline__ void cpa16(unsigned s, const float* g) {
    asm volatile("cp.async.cg.shared.global [%0], [%1], 16;" :: "r"(s), "l"(g));
}

// ---------------- weight pre-pack --------------------------------------------
__global__ void k_packW(const float* __restrict__ W, float* __restrict__ PW,
                        int K, int M) {
    int i = blockIdx.x * blockDim.x + threadIdx.x;
    int tot = K * M;
    if (i >= tot) return;
    const float* w = W + (size_t)blockIdx.y * tot;
    float* pw = PW + (size_t)blockIdx.y * tot;
    int k = i / M, m = i - k * M;
    pw[pk_b(k, m, M)] = f2tf(w[i]);
}

// fused QKV pack: [E, 1152] from Wq|Wk|Wv each [L,E,E]
__global__ void k_packQKV(const float* __restrict__ Wq, const float* __restrict__ Wk,
                          const float* __restrict__ Wv, float* __restrict__ PW) {
    int i = blockIdx.x * blockDim.x + threadIdx.x;
    const int tot = EE * QKVM;
    if (i >= tot) return;
    int l = blockIdx.y;
    int k = i / QKVM, m = i - k * QKVM;
    float v;
    if (m < EE)            v = Wq[(size_t)l * EE * EE + (size_t)k * EE + m];
    else if (m < 2 * EE)   v = Wk[(size_t)l * EE * EE + (size_t)k * EE + (m - EE)];
    else                   v = Wv[(size_t)l * EE * EE + (size_t)k * EE + (m - 2 * EE)];
    PW[(size_t)l * tot + pk_b(k, m, QKVM)] = f2tf(v);
}

// LM head pack: [384, 65] -> padded packed [384, 128]
__global__ void k_packWlm(const float* __restrict__ W, float* __restrict__ PW) {
    int i = blockIdx.x * blockDim.x + threadIdx.x;
    if (i >= EE * 128) return;
    int k = i / 128, m = i - k * 128;
    float v = (m < VV) ? W[(size_t)k * VV + m] : 0.f;
    PW[pk_b(k, m, 128)] = f2tf(v);
}

// ---------------- embedding --------------------------------------------------
__global__ void k_embed(const int* __restrict__ idx, const float* __restrict__ tok,
                        const float* __restrict__ pos, float* __restrict__ x) {
    int i = blockIdx.x * blockDim.x + threadIdx.x;
    if (i >= NTOK * EE) return;
    int n = i / EE, e = i - n * EE;
    int t = n % TT;
    x[i] = tok[idx[n] * EE + e] + pos[t * EE + e];
}

// ---------------- LayerNorm (natural in, packed tf32 out) --------------------
__global__ void k_ln(const float* __restrict__ x, const float* __restrict__ g,
                     const float* __restrict__ b, float* __restrict__ y) {
    int warp = threadIdx.x >> 5, lane = threadIdx.x & 31;
    int row = blockIdx.x * 8 + warp;
    if (row >= NTOK) return;
    const float4* xr = (const float4*)(x + (size_t)row * EE);
    float4 v[3];
#pragma unroll
    for (int i = 0; i < 3; i++) v[i] = xr[lane + i * 32];
    float s = 0.f, s2 = 0.f;
#pragma unroll
    for (int i = 0; i < 3; i++) {
        s  += v[i].x + v[i].y + v[i].z + v[i].w;
        s2 += v[i].x * v[i].x + v[i].y * v[i].y + v[i].z * v[i].z + v[i].w * v[i].w;
    }
#pragma unroll
    for (int off = 16; off > 0; off >>= 1) {
        s  += __shfl_xor_sync(0xffffffffu, s,  off);
        s2 += __shfl_xor_sync(0xffffffffu, s2, off);
    }
    float mu = s * (1.f / EE);
    float var = s2 * (1.f / EE) - mu * mu;
    float rs = rsqrtf(var + 1e-5f);
    const float4* gr = (const float4*)g;
    const float4* br = (const float4*)b;
#pragma unroll
    for (int i = 0; i < 3; i++) {
        float4 gg = gr[lane + i * 32], bb = br[lane + i * 32];
        float o0 = (v[i].x - mu) * rs * gg.x + bb.x;
        float o1 = (v[i].y - mu) * rs * gg.y + bb.y;
        float o2 = (v[i].z - mu) * rs * gg.z + bb.z;
        float o3 = (v[i].w - mu) * rs * gg.w + bb.w;
        int cb = (lane + i * 32) * 4;
        y[pk_a(row, cb + 0, EE)] = f2tf(o0);
        y[pk_a(row, cb + 1, EE)] = f2tf(o1);
        y[pk_a(row, cb + 2, EE)] = f2tf(o2);
        y[pk_a(row, cb + 3, EE)] = f2tf(o3);
    }
}

// ---------------- tf32 tensor-core GEMM, packed inputs -----------------------
// flags: 1=relu, 2=packed output
__global__ void __launch_bounds__(256, 2) k_gemm_tc2(
    const float* __restrict__ PA, const float* __restrict__ PB,
    const float* __restrict__ bias, const float* __restrict__ res,
    float* __restrict__ C, int K, int M, int flags)
{
    extern __shared__ float smem[];
    const int n0 = blockIdx.y * 128;
    const int m0 = blockIdx.x * 128;
    const int tid  = threadIdx.x;
    const int lane = tid & 31, warp = tid >> 5;
    const int wm = warp & 1, wn = warp >> 1;
    const int gid = lane >> 2, tig = lane & 3;
    const int K8 = K >> 3, M8 = M >> 3;
    const int KB = K >> 5;

    const float* gA[4]; const float* gB[4];
    unsigned sA[4], sB[4];
#pragma unroll
    for (int i = 0; i < 4; i++) {
        int ch = tid + i * 256;
        int mt = ch >> 7, kt = (ch >> 5) & 3, c4 = ch & 31;
        sA[i] = (unsigned)(((mt * 4 + kt) * 128 + c4 * 4) * 4);
        gA[i] = PA + ((size_t)((n0 >> 4) + mt) * K8 + kt) * 128 + c4 * 4;
        int bkt = ch >> 8, nt = (ch >> 4) & 15, d4 = ch & 15;
        sB[i] = (unsigned)((4096 + (bkt * 16 + nt) * 64 + d4 * 4) * 4);
        gB[i] = PB + ((size_t)bkt * M8 + (m0 >> 3) + nt) * 64 + d4 * 4;
    }
    const int strA = 512;
    const int strB = 32 * M;

    unsigned smem_u = (unsigned)__cvta_generic_to_shared(smem);
    auto issue = [&](int ks, int buf) {
        unsigned base = smem_u + (unsigned)buf * 8192u * 4u;
#pragma unroll
        for (int i = 0; i < 4; i++) cpa16(base + sA[i], gA[i] + (size_t)ks * strA);
#pragma unroll
        for (int i = 0; i < 4; i++) cpa16(base + sB[i], gB[i] + (size_t)ks * strB);
    };

    float acc[4][4][4];
#pragma unroll
    for (int a = 0; a < 4; a++)
#pragma unroll
        for (int b = 0; b < 4; b++)
#pragma unroll
            for (int c = 0; c < 4; c++) acc[a][b][c] = 0.f;

    issue(0, 0);
    asm volatile("cp.async.commit_group;" ::: "memory");
    issue(1, 1);
    asm volatile("cp.async.commit_group;" ::: "memory");

    int p = 0;
    for (int kb = 0; kb < KB; kb++) {
        asm volatile("cp.async.wait_group 1;" ::: "memory");
        __syncthreads();
        if (kb + 2 < KB) issue(kb + 2, (kb + 2) % 3);
        asm volatile("cp.async.commit_group;" ::: "memory");

        const float* as = smem + p * 8192;
        const float* bs = as + 4096;
#pragma unroll
        for (int kt = 0; kt < 4; kt++) {
            unsigned af[4][4], bf[4][2];
#pragma unroll
            for (int mi = 0; mi < 4; mi++) {
                float4 v = *(const float4*)&as[((((wm * 4 + mi) * 4) + kt) << 7) + (lane << 2)];
                af[mi][0] = __float_as_uint(v.x); af[mi][1] = __float_as_uint(v.y);
                af[mi][2] = __float_as_uint(v.z); af[mi][3] = __float_as_uint(v.w);
            }
#pragma unroll
            for (int ni = 0; ni < 4; ni++) {
                float2 v = *(const float2*)&bs[(((kt * 16) + (wn * 4 + ni)) << 6) + (lane << 1)];
                bf[ni][0] = __float_as_uint(v.x); bf[ni][1] = __float_as_uint(v.y);
            }
#pragma unroll
            for (int mi = 0; mi < 4; mi++)
#pragma unroll
                for (int ni = 0; ni < 4; ni++) {
                    asm volatile(
                        "mma.sync.aligned.m16n8k8.row.col.f32.tf32.tf32.f32 "
                        "{%0,%1,%2,%3}, {%4,%5,%6,%7}, {%8,%9}, {%0,%1,%2,%3};"
                        : "+f"(acc[mi][ni][0]), "+f"(acc[mi][ni][1]),
                          "+f"(acc[mi][ni][2]), "+f"(acc[mi][ni][3])
                        : "r"(af[mi][0]), "r"(af[mi][1]), "r"(af[mi][2]), "r"(af[mi][3]),
                          "r"(bf[ni][0]), "r"(bf[ni][1]));
                }
        }
        p = (p == 2) ? 0 : p + 1;
    }

    const bool relu = (flags & 1), pko = (flags & 2);
#pragma unroll
    for (int mi = 0; mi < 4; mi++) {
        int row = n0 + (wm << 6) + (mi << 4) + gid;
#pragma unroll
        for (int ni = 0; ni < 4; ni++) {
            int col = m0 + (wn << 5) + (ni << 3) + (tig << 1);
            float b0 = 0.f, b1 = 0.f;
            if (bias) { b0 = bias[col]; b1 = bias[col + 1]; }
            float v0 = acc[mi][ni][0] + b0;
            float v1 = acc[mi][ni][1] + b1;
            float v2 = acc[mi][ni][2] + b0;
            float v3 = acc[mi][ni][3] + b1;
            if (res) {
                const float* r0 = res + (size_t)row * M + col;
                const float* r1 = res + (size_t)(row + 8) * M + col;
                v0 += r0[0]; v1 += r0[1]; v2 += r1[0]; v3 += r1[1];
            }
            if (relu) {
                v0 = fmaxf(v0, 0.f); v1 = fmaxf(v1, 0.f);
                v2 = fmaxf(v2, 0.f); v3 = fmaxf(v3, 0.f);
            }
            if (pko) {
                C[pk_a(row,     col,     M)] = f2tf(v0);
                C[pk_a(row,     col + 1, M)] = f2tf(v1);
                C[pk_a(row + 8, col,     M)] = f2tf(v2);
                C[pk_a(row + 8, col + 1, M)] = f2tf(v3);
            } else {
                *(float2*)(C + (size_t)row * M + col)       = make_float2(v0, v1);
                *(float2*)(C + (size_t)(row + 8) * M + col) = make_float2(v2, v3);
            }
        }
    }
}

// ---------------- causal attention: fused-QKV in (stride 1152), 2-key ILP ----
__global__ void __launch_bounds__(256) k_attn(
    const float* __restrict__ QKV, float* __restrict__ O)
{
    __shared__ float Ks[64][64];
    __shared__ float Vs[64][64];
    const int hd = blockIdx.x, b = blockIdx.y;
    const int tq = threadIdx.x;
    const float scale = 0.125f;

    float4 q4[16], o4[16];
    const float4* qr = (const float4*)(QKV + (size_t)(b * TT + tq) * QKVM + hd * DD);
#pragma unroll
    for (int i = 0; i < 16; i++) { q4[i] = qr[i]; o4[i] = make_float4(0.f, 0.f, 0.f, 0.f); }
    float m = -INFINITY, l = 0.f;

    for (int c = 0; c < 4; c++) {
#pragma unroll
        for (int i = 0; i < 4; i++) {
            int idx = threadIdx.x + i * 256;
            int r = idx >> 4, d4 = idx & 15;
            size_t goff = (size_t)(b * TT + c * 64 + r) * QKVM + hd * DD;
            ((float4*)&Ks[r][0])[d4] = ((const float4*)(QKV + goff + EE))[d4];
            ((float4*)&Vs[r][0])[d4] = ((const float4*)(QKV + goff + 2 * EE))[d4];
        }
        __syncthreads();
        int rel = tq - c * 64;
        if (rel >= 0) {
            int kend = rel + 1; if (kend > 64) kend = 64;
            int kk = 0;
            for (; kk + 1 < kend; kk += 2) {
                const float4* kr0 = (const float4*)&Ks[kk][0];
                const float4* kr1 = (const float4*)&Ks[kk + 1][0];
                float s0 = 0.f, s1 = 0.f;
#pragma unroll
                for (int i = 0; i < 16; i++) {
                    float4 k0 = kr0[i], k1 = kr1[i], qv = q4[i];
                    s0 += qv.x * k0.x + qv.y * k0.y + qv.z * k0.z + qv.w * k0.w;
                    s1 += qv.x * k1.x + qv.y * k1.y + qv.z * k1.z + qv.w * k1.w;
                }
                s0 *= scale; s1 *= scale;
                float mn = fmaxf(m, fmaxf(s0, s1));
                float al = __expf(m - mn);
                float p0 = __expf(s0 - mn);
                float p1 = __expf(s1 - mn);
                l = l * al + p0 + p1;
                const float4* vr0 = (const float4*)&Vs[kk][0];
                const float4* vr1 = (const float4*)&Vs[kk + 1][0];
#pragma unroll
                for (int i = 0; i < 16; i++) {
                    float4 v0 = vr0[i], v1 = vr1[i];
                    o4[i].x = o4[i].x * al + p0 * v0.x + p1 * v1.x;
                    o4[i].y = o4[i].y * al + p0 * v0.y + p1 * v1.y;
                    o4[i].z = o4[i].z * al + p0 * v0.z + p1 * v1.z;
                    o4[i].w = o4[i].w * al + p0 * v0.w + p1 * v1.w;
                }
                m = mn;
            }
            if (kk < kend) {
                const float4* kr = (const float4*)&Ks[kk][0];
                float s = 0.f;
#pragma unroll
                for (int i = 0; i < 16; i++) {
                    float4 kv = kr[i];
                    s += q4[i].x * kv.x + q4[i].y * kv.y + q4[i].z * kv.z + q4[i].w * kv.w;
                }
                s *= scale;
                float mn = fmaxf(m, s);
                float pp = __expf(s - mn);
                float al = __expf(m - mn);
                l = l * al + pp;
                const float4* vr = (const float4*)&Vs[kk][0];
#pragma unroll
                for (int i = 0; i < 16; i++) {
                    float4 vv = vr[i];
                    o4[i].x = o4[i].x * al + pp * vv.x;
                    o4[i].y = o4[i].y * al + pp * vv.y;
                    o4[i].z = o4[i].z * al + pp * vv.z;
                    o4[i].w = o4[i].w * al + pp * vv.w;
                }
                m = mn;
            }
        }
        __syncthreads();
    }
    float inv = 1.f / l;
    int rowR = b * TT + tq;
#pragma unroll
    for (int i = 0; i < 16; i++) {
        int cb = hd * DD + i * 4;
        O[pk_a(rowR, cb + 0, EE)] = f2tf(o4[i].x * inv);
        O[pk_a(rowR, cb + 1, EE)] = f2tf(o4[i].y * inv);
        O[pk_a(rowR, cb + 2, EE)] = f2tf(o4[i].z * inv);
        O[pk_a(rowR, cb + 3, EE)] = f2tf(o4[i].w * inv);
    }
}

// ---------------- LM head compact: padded [N,128] -> [N,65] + bias -----------
__global__ void k_head_compact(const float* __restrict__ C128,
                               const float* __restrict__ blm,
                               float* __restrict__ logits) {
    int i = blockIdx.x * blockDim.x + threadIdx.x;
    if (i >= NTOK * VV) return;
    int n = i / VV, m = i - n * VV;
    logits[i] = C128[(size_t)n * 128 + m] + blm[m];
}

// ---------------- loss -------------------------------------------------------
__global__ void k_zero(float* loss) { *loss = 0.f; }

__global__ void k_loss(const float* __restrict__ logits, const int* __restrict__ tgt,
                       float* __restrict__ loss) {
    int warp = threadIdx.x >> 5, lane = threadIdx.x & 31;
    int row = blockIdx.x * 8 + warp;
    if (row >= NTOK) return;
    const float* lr = logits + (size_t)row * VV;
    float x0 = (lane < VV)      ? lr[lane]      : -INFINITY;
    float x1 = (lane + 32 < VV) ? lr[lane + 32] : -INFINITY;
    float x2 = (lane + 64 < VV) ? lr[lane + 64] : -INFINITY;
    float mx = fmaxf(x0, fmaxf(x1, x2));
#pragma unroll
    for (int off = 16; off > 0; off >>= 1) mx = fmaxf(mx, __shfl_xor_sync(0xffffffffu, mx, off));
    float se = 0.f;
    if (lane < VV)      se += expf(x0 - mx);
    if (lane + 32 < VV) se += expf(x1 - mx);
    if (lane + 64 < VV) se += expf(x2 - mx);
#pragma unroll
    for (int off = 16; off > 0; off >>= 1) se += __shfl_xor_sync(0xffffffffu, se, off);
    if (lane == 0) {
        float lt = lr[tgt[row]];
        atomicAdd(loss, mx + logf(se) - lt);
    }
}

__global__ void k_final(const float* __restrict__ loss, float* __restrict__ out) {
    out[0] = *loss * (1.f / NTOK);
}

// ---------------- host -------------------------------------------------------
extern "C" void kernel_launch(void* const* d_in, const int* in_sizes, int n_in,
                              void* d_out, int out_size) {
    const int*   idx  = (const int*)  d_in[0];
    const int*   tgt  = (const int*)  d_in[1];
    const float* tok  = (const float*)d_in[2];
    const float* pos  = (const float*)d_in[3];
    const float* Wq   = (const float*)d_in[4];
    const float* Wk   = (const float*)d_in[5];
    const float* Wv   = (const float*)d_in[6];
    const float* Wo   = (const float*)d_in[7];
    const float* bo   = (const float*)d_in[8];
    const float* W1   = (const float*)d_in[9];
    const float* b1   = (const float*)d_in[10];
    const float* W2   = (const float*)d_in[11];
    const float* b2w  = (const float*)d_in[12];
    const float* ln1g = (const float*)d_in[13];
    const float* ln1b = (const float*)d_in[14];
    const float* ln2g = (const float*)d_in[15];
    const float* ln2b = (const float*)d_in[16];
    const float* lnfg = (const float*)d_in[17];
    const float* lnfb = (const float*)d_in[18];
    const float* Wlm  = (const float*)d_in[19];
    const float* blm  = (const float*)d_in[20];

    float *x, *h, *qkv, *att, *f, *glog, *gloss, *pw;
    cudaGetSymbolAddress((void**)&x,    g_x);
    cudaGetSymbolAddress((void**)&h,    g_h);
    cudaGetSymbolAddress((void**)&qkv,  g_qkv);
    cudaGetSymbolAddress((void**)&att,  g_att);
    cudaGetSymbolAddress((void**)&f,    g_f);
    cudaGetSymbolAddress((void**)&glog, g_logits);
    cudaGetSymbolAddress((void**)&gloss, g_loss);
    cudaGetSymbolAddress((void**)&pw,   g_pw);

    static int smem_set = 0;
    if (!smem_set) {
        cudaFuncSetAttribute(k_gemm_tc2, cudaFuncAttributeMaxDynamicSharedMemorySize, 98304);
        smem_set = 1;
    }

    const size_t EExEE = (size_t)EE * EE, EExFF = (size_t)EE * FF, EExQ = (size_t)EE * QKVM;
    float* pqkv = pw;
    float* pwo  = pqkv + (size_t)LLAY * EExQ;
    float* pw1  = pwo  + (size_t)LLAY * EExEE;
    float* pw2  = pw1  + (size_t)LLAY * EExFF;
    float* pwlm = pw2  + (size_t)LLAY * EExFF;

    k_packQKV<<<dim3((EE * QKVM + 255) / 256, LLAY), 256>>>(Wq, Wk, Wv, pqkv);
    k_packW<<<dim3((EE * EE + 255) / 256, LLAY), 256>>>(Wo, pwo, EE, EE);
    k_packW<<<dim3((EE * FF + 255) / 256, LLAY), 256>>>(W1, pw1, EE, FF);
    k_packW<<<dim3((EE * FF + 255) / 256, LLAY), 256>>>(W2, pw2, FF, EE);
    k_packWlm<<<(EE * 128 + 255) / 256, 256>>>(Wlm, pwlm);

    float* outf   = (float*)d_out;
    float* logits = (out_size >= NTOK * VV) ? outf : glog;

    k_embed<<<(NTOK * EE + 255) / 256, 256>>>(idx, tok, pos, x);

    dim3 gQ(QKVM / 128, NTOK / 128);  // (9,128)
    dim3 gE(EE / 128, NTOK / 128);    // (3,128)
    dim3 gF(FF / 128, NTOK / 128);    // (12,128)
    dim3 gLN(NTOK / 8);
    const int DSM = 98304;

    for (int l = 0; l < LLAY; l++) {
        k_ln<<<gLN, 256>>>(x, ln1g + l * EE, ln1b + l * EE, h);
        k_gemm_tc2<<<gQ, 256, DSM>>>(h, pqkv + (size_t)l * EExQ, nullptr, nullptr, qkv, EE, QKVM, 0);
        k_attn<<<dim3(HH, BB), 256>>>(qkv, att);
        k_gemm_tc2<<<gE, 256, DSM>>>(att, pwo + (size_t)l * EExEE, bo + l * EE, x, x, EE, EE, 0);
        k_ln<<<gLN, 256>>>(x, ln2g + l * EE, ln2b + l * EE, h);
        k_gemm_tc2<<<gF, 256, DSM>>>(h, pw1 + (size_t)l * EExFF, b1 + l * FF, nullptr, f, EE, FF, 1 | 2);
        k_gemm_tc2<<<gE, 256, DSM>>>(f, pw2 + (size_t)l * EExFF, b2w + l * EE, x, x, FF, EE, 0);
    }

    k_ln<<<gLN, 256>>>(x, lnfg, lnfb, h);
    k_gemm_tc2<<<dim3(1, NTOK / 128), 256, DSM>>>(h, pwlm, nullptr, nullptr, f, EE, 128, 0);
    k_head_compact<<<(NTOK * VV + 255) / 256, 256>>>(f, blm, logits);

    if (out_size == 1 || out_size > NTOK * VV) {
        k_zero<<<1, 1>>>(gloss);
        k_loss<<<NTOK / 8, 256>>>(logits, tgt, gloss);
        float* ldst = (out_size == 1) ? outf : (outf + NTOK * VV);
        k_final<<<1, 1>>>(gloss, ldst);
    }
}